// round 1
// baseline (speedup 1.0000x reference)
#include <cuda_runtime.h>

// Gibbs sweep over DIM=32 coordinates of B rows.
// x_i <- mu_i - (sum_{j!=i} P_ij x_j)/P_ii + sqrt(1/P_ii)*n_i
// Rewritten with A_ij = -P_ij/P_ii (diag 0), base_i = mu_i + sigma_i*n_i:
//   x_i <- base_i + sum_j A_ij x_j
// One thread owns 2 rows in registers; dot products use packed fma.rn.f32x2.

#define DIM 32
#define THREADS 64            // 2 warps / block
#define ROWS_PER_WARP 64      // 32 lanes * 2 rows
#define ROWS_PER_BLOCK 128

__device__ __forceinline__ unsigned long long f2u(float2 v) {
    unsigned long long u; __builtin_memcpy(&u, &v, 8); return u;
}
__device__ __forceinline__ float2 u2f(unsigned long long u) {
    float2 v; __builtin_memcpy(&v, &u, 8); return v;
}
__device__ __forceinline__ float2 ffma2(float2 a, float2 b, float2 c) {
    unsigned long long d;
    asm("fma.rn.f32x2 %0, %1, %2, %3;"
        : "=l"(d) : "l"(f2u(a)), "l"(f2u(b)), "l"(f2u(c)));
    return u2f(d);
}
__device__ __forceinline__ float2 fadd2(float2 a, float2 b) {
    unsigned long long d;
    asm("add.rn.f32x2 %0, %1, %2;"
        : "=l"(d) : "l"(f2u(a)), "l"(f2u(b)));
    return u2f(d);
}

__global__ __launch_bounds__(THREADS)
void gibbs_sweep_kernel(const float* __restrict__ x,
                        const float* __restrict__ noise,
                        const float* __restrict__ P,
                        const float* __restrict__ mu,
                        float* __restrict__ out,
                        int B)
{
    __shared__ float Asm[DIM * DIM];          // A_ij = -P_ij/P_ii, diag 0
    __shared__ float invs[DIM];
    __shared__ float4 sg4[DIM / 4];           // sigma_i packed by 4
    __shared__ float4 mu4[DIM / 4];           // mu_i packed by 4
    // Per-warp staging buffer, reused three times:
    //  (1) x transpose-stage  : float4[64*8], XOR-swizzled      (8192 B)
    //  (2) base = mu+sig*n    : float [64*33], pad-33 layout    (8448 B)
    //  (3) out transpose-stage: float4[64*8], XOR-swizzled
    __shared__ __align__(16) float buf[2][ROWS_PER_WARP * 33];

    const int tid = threadIdx.x;

    // ---- per-block precompute: coefficients ----
    if (tid < DIM) {
        float pii = P[tid * DIM + tid];
        float inv = 1.0f / pii;
        invs[tid] = inv;
        ((float*)sg4)[tid] = sqrtf(inv);
        ((float*)mu4)[tid] = mu[tid];
    }
    __syncthreads();
    // ---- per-block precompute: A matrix (coalesced global reads) ----
    #pragma unroll
    for (int k = 0; k < (DIM * DIM) / THREADS; ++k) {
        int e = k * THREADS + tid;
        int r = e >> 5, c = e & 31;
        float v = P[e] * (-invs[r]);
        Asm[e] = (r == c) ? 0.0f : v;
    }
    __syncthreads();

    const int warp = tid >> 5;
    const int lane = tid & 31;
    const int R0   = (blockIdx.x * 2 + warp) * ROWS_PER_WARP;
    const int c4   = lane & 7;     // which float4 of a row this lane moves
    const int rb   = lane >> 3;    // row sub-offset within a group of 4
    float4* st4 = (float4*)buf[warp];
    float*  stf = buf[warp];

    // ---- stage x: coalesced LDG -> swizzled SMEM ----
    const float4* gx = (const float4*)x;
    #pragma unroll
    for (int k = 0; k < 16; ++k) {
        int row = k * 4 + rb;
        int gr  = R0 + row;
        float4 v = (gr < B) ? gx[gr * 8 + c4] : make_float4(0.f, 0.f, 0.f, 0.f);
        st4[row * 8 + (c4 ^ (row & 7))] = v;
    }
    __syncwarp();

    // ---- gather my two rows into registers (conflict-free swizzled LDS.128) ----
    const int sw = lane & 7;
    float2 xA[16], xB[16];
    #pragma unroll
    for (int c = 0; c < 8; ++c) {
        float4 v = st4[lane * 8 + (c ^ sw)];
        xA[2 * c]     = make_float2(v.x, v.y);
        xA[2 * c + 1] = make_float2(v.z, v.w);
        float4 w = st4[(lane + 32) * 8 + (c ^ sw)];
        xB[2 * c]     = make_float2(w.x, w.y);
        xB[2 * c + 1] = make_float2(w.z, w.w);
    }
    __syncwarp();

    // ---- stage base = mu + sigma*noise into pad-33 layout (reuses buf) ----
    const float4* gn = (const float4*)noise;
    const float4 sgv = sg4[c4];
    const float4 muv = mu4[c4];
    #pragma unroll
    for (int k = 0; k < 16; ++k) {
        int row = k * 4 + rb;
        int gr  = R0 + row;
        float4 n4 = (gr < B) ? gn[gr * 8 + c4] : make_float4(0.f, 0.f, 0.f, 0.f);
        float* d = stf + row * 33 + c4 * 4;
        d[0] = fmaf(sgv.x, n4.x, muv.x);
        d[1] = fmaf(sgv.y, n4.y, muv.y);
        d[2] = fmaf(sgv.z, n4.z, muv.z);
        d[3] = fmaf(sgv.w, n4.w, muv.w);
    }
    __syncwarp();

    const float* pA = stf + lane * 33;
    const float* pB = stf + (lane + 32) * 33;
    const float4* A4 = (const float4*)Asm;

    // ---- the sequential sweep, fully unrolled (compile-time register indexing) ----
    #pragma unroll
    for (int i = 0; i < DIM; ++i) {
        float2 a0 = make_float2(0.f, 0.f), a1 = make_float2(0.f, 0.f);
        float2 b0 = make_float2(0.f, 0.f), b1 = make_float2(0.f, 0.f);
        #pragma unroll
        for (int t = 0; t < 8; ++t) {
            float4 p = A4[i * 8 + t];            // broadcast LDS.128
            float2 p0 = make_float2(p.x, p.y);
            float2 p1 = make_float2(p.z, p.w);
            a0 = ffma2(xA[2 * t],     p0, a0);
            a1 = ffma2(xA[2 * t + 1], p1, a1);
            b0 = ffma2(xB[2 * t],     p0, b0);
            b1 = ffma2(xB[2 * t + 1], p1, b1);
        }
        float2 sa = fadd2(a0, a1);
        float2 sb = fadd2(b0, b1);
        float nA = (sa.x + sa.y) + pA[i];
        float nB = (sb.x + sb.y) + pB[i];
        if (i & 1) { xA[i >> 1].y = nA; xB[i >> 1].y = nB; }
        else       { xA[i >> 1].x = nA; xB[i >> 1].x = nB; }
    }

    __syncwarp();
    // ---- scatter rows back to swizzled SMEM, then coalesced STG ----
    #pragma unroll
    for (int c = 0; c < 8; ++c) {
        st4[lane * 8 + (c ^ sw)] =
            make_float4(xA[2 * c].x, xA[2 * c].y, xA[2 * c + 1].x, xA[2 * c + 1].y);
        st4[(lane + 32) * 8 + (c ^ sw)] =
            make_float4(xB[2 * c].x, xB[2 * c].y, xB[2 * c + 1].x, xB[2 * c + 1].y);
    }
    __syncwarp();
    float4* gout = (float4*)out;
    #pragma unroll
    for (int k = 0; k < 16; ++k) {
        int row = k * 4 + rb;
        int gr  = R0 + row;
        if (gr < B) gout[gr * 8 + c4] = st4[row * 8 + (c4 ^ (row & 7))];
    }
}

extern "C" void kernel_launch(void* const* d_in, const int* in_sizes, int n_in,
                              void* d_out, int out_size)
{
    const float* x     = (const float*)d_in[0];
    const float* noise = (const float*)d_in[1];
    const float* P     = (const float*)d_in[2];
    const float* mu    = (const float*)d_in[3];
    float* out = (float*)d_out;

    int B = in_sizes[0] / DIM;
    int grid = (B + ROWS_PER_BLOCK - 1) / ROWS_PER_BLOCK;
    gibbs_sweep_kernel<<<grid, THREADS>>>(x, noise, P, mu, out, B);
}

// round 3
// speedup vs baseline: 3.3604x; 3.3604x over previous
#include <cuda_runtime.h>

// Gibbs sweep over DIM=32 coordinates of B rows.
// x_i <- base_i + sum_j A_ij x_j,   A_ij = -P_ij/P_ii (diag 0),
// base_i = mu_i + sqrt(1/P_ii)*n_i.
// One thread owns ONE row (32 floats = 16 float2 in regs); packed fma.rn.f32x2.
// Coalesced global IO via swizzled SMEM transpose staging.

#define DIM 32
#define THREADS 128
#define ROWS_PER_BLOCK 128

__device__ __forceinline__ unsigned long long f2u(float2 v) {
    unsigned long long u; __builtin_memcpy(&u, &v, 8); return u;
}
__device__ __forceinline__ float2 u2f(unsigned long long u) {
    float2 v; __builtin_memcpy(&v, &u, 8); return v;
}
__device__ __forceinline__ float2 ffma2(float2 a, float2 b, float2 c) {
    unsigned long long d;
    asm("fma.rn.f32x2 %0, %1, %2, %3;"
        : "=l"(d) : "l"(f2u(a)), "l"(f2u(b)), "l"(f2u(c)));
    return u2f(d);
}
__device__ __forceinline__ float2 fadd2(float2 a, float2 b) {
    unsigned long long d;
    asm("add.rn.f32x2 %0, %1, %2;"
        : "=l"(d) : "l"(f2u(a)), "l"(f2u(b)));
    return u2f(d);
}

__global__ __launch_bounds__(THREADS, 5)
void gibbs_sweep_kernel(const float* __restrict__ x,
                        const float* __restrict__ noise,
                        const float* __restrict__ P,
                        const float* __restrict__ mu,
                        float* __restrict__ out,
                        int B)
{
    __shared__ float Asm[DIM * DIM];           // A_ij = -P_ij/P_ii, diag 0
    __shared__ float invs[DIM];
    __shared__ float sgf[DIM];                 // sigma_i
    __shared__ float muf[DIM];
    // One buffer, reused:
    //  (a) x transpose-stage : float4[128*8], XOR-swizzled  (16 KB)
    //  (b) base = mu+sig*n   : float [128*33], pad-33       (16.9 KB)
    //  (c) out transpose-stage (same layout as (a))
    __shared__ __align__(16) float buf[ROWS_PER_BLOCK * 33];

    const int tid = threadIdx.x;

    // ---- per-block precompute ----
    if (tid < DIM) {
        float pii = P[tid * DIM + tid];
        float inv = 1.0f / pii;
        invs[tid] = inv;
        sgf[tid]  = sqrtf(inv);
        muf[tid]  = mu[tid];
    }
    __syncthreads();
    #pragma unroll
    for (int k = 0; k < (DIM * DIM) / THREADS; ++k) {
        int e = k * THREADS + tid;
        int r = e >> 5, c = e & 31;
        float v = P[e] * (-invs[r]);
        Asm[e] = (r == c) ? 0.0f : v;
    }
    __syncthreads();

    const int R0 = blockIdx.x * ROWS_PER_BLOCK;
    float4* st4 = (float4*)buf;

    // ---- stage x: coalesced LDG.128 -> swizzled SMEM (bank = 8*(row%4)+c', full 32) ----
    const float4* gx = (const float4*)x;
    #pragma unroll
    for (int k = 0; k < 8; ++k) {
        int idx = k * THREADS + tid;           // 0..1023 linear, coalesced
        int row = idx >> 3;
        int c   = idx & 7;
        int gr  = R0 + row;
        float4 v = (gr < B) ? gx[(size_t)gr * 8 + c]
                            : make_float4(0.f, 0.f, 0.f, 0.f);
        st4[row * 8 + (c ^ ((row >> 2) & 7))] = v;
    }
    __syncthreads();

    // ---- gather my row into registers (conflict-free swizzled LDS.128) ----
    const int sw = (tid >> 2) & 7;
    float2 s[16];
    #pragma unroll
    for (int c = 0; c < 8; ++c) {
        float4 v = st4[tid * 8 + (c ^ sw)];
        s[2 * c]     = make_float2(v.x, v.y);
        s[2 * c + 1] = make_float2(v.z, v.w);
    }
    __syncthreads();

    // ---- stage base = mu + sigma*noise into pad-33 layout (reuses buf) ----
    const float4* gn = (const float4*)noise;
    #pragma unroll
    for (int k = 0; k < 8; ++k) {
        int idx = k * THREADS + tid;
        int row = idx >> 3;
        int c   = idx & 7;
        int gr  = R0 + row;
        float4 n4 = (gr < B) ? gn[(size_t)gr * 8 + c]
                             : make_float4(0.f, 0.f, 0.f, 0.f);
        float* d = buf + row * 33 + c * 4;
        d[0] = fmaf(sgf[c * 4 + 0], n4.x, muf[c * 4 + 0]);
        d[1] = fmaf(sgf[c * 4 + 1], n4.y, muf[c * 4 + 1]);
        d[2] = fmaf(sgf[c * 4 + 2], n4.z, muf[c * 4 + 2]);
        d[3] = fmaf(sgf[c * 4 + 3], n4.w, muf[c * 4 + 3]);
    }
    __syncthreads();

    const float* pb = buf + tid * 33;          // my base row (stride-33, conflict-free)
    const float4* A4 = (const float4*)Asm;

    // ---- the sequential sweep, fully unrolled (constant register indexing) ----
    #pragma unroll
    for (int i = 0; i < DIM; ++i) {
        float2 a0 = make_float2(0.f, 0.f), a1 = make_float2(0.f, 0.f);
        float2 a2 = make_float2(0.f, 0.f), a3 = make_float2(0.f, 0.f);
        #pragma unroll
        for (int t = 0; t < 4; ++t) {
            float4 p = A4[i * 8 + 2 * t];        // broadcast LDS.128
            float4 q = A4[i * 8 + 2 * t + 1];
            a0 = ffma2(s[4 * t],     make_float2(p.x, p.y), a0);
            a1 = ffma2(s[4 * t + 1], make_float2(p.z, p.w), a1);
            a2 = ffma2(s[4 * t + 2], make_float2(q.x, q.y), a2);
            a3 = ffma2(s[4 * t + 3], make_float2(q.z, q.w), a3);
        }
        float2 sa = fadd2(fadd2(a0, a1), fadd2(a2, a3));
        float nv = (sa.x + sa.y) + pb[i];
        if (i & 1) s[i >> 1].y = nv;
        else       s[i >> 1].x = nv;
    }

    __syncthreads();   // sweep done everywhere before clobbering base region
    // ---- scatter row back to swizzled SMEM, then coalesced STG.128 ----
    #pragma unroll
    for (int c = 0; c < 8; ++c) {
        st4[tid * 8 + (c ^ sw)] =
            make_float4(s[2 * c].x, s[2 * c].y, s[2 * c + 1].x, s[2 * c + 1].y);
    }
    __syncthreads();
    float4* gout = (float4*)out;
    #pragma unroll
    for (int k = 0; k < 8; ++k) {
        int idx = k * THREADS + tid;
        int row = idx >> 3;
        int c   = idx & 7;
        int gr  = R0 + row;
        if (gr < B) gout[(size_t)gr * 8 + c] = st4[row * 8 + (c ^ ((row >> 2) & 7))];
    }
}

extern "C" void kernel_launch(void* const* d_in, const int* in_sizes, int n_in,
                              void* d_out, int out_size)
{
    const float* x     = (const float*)d_in[0];
    const float* noise = (const float*)d_in[1];
    const float* P     = (const float*)d_in[2];
    const float* mu    = (const float*)d_in[3];
    float* out = (float*)d_out;

    int B = in_sizes[0] / DIM;
    int grid = (B + ROWS_PER_BLOCK - 1) / ROWS_PER_BLOCK;
    gibbs_sweep_kernel<<<grid, THREADS>>>(x, noise, P, mu, out, B);
}